// round 13
// baseline (speedup 1.0000x reference)
#include <cuda_runtime.h>
#include <cuda_bf16.h>
#include <math.h>

#define BS   16
#define NA   8400
#define NMAX 64
#define NC   80
#define TOPK 13
#define EPSF 1e-9f
#define PIF  3.14159265358979323846f

// Output layout (flattened, reference return order, all f32)
#define LAB_OFF 0
#define CIR_OFF (BS*NA)                 // 134400
#define SC_OFF  (CIR_OFF + BS*NA*3)     // 537600
#define FG_OFF  (SC_OFF  + BS*NA*NC)    // 11289600
#define TGT_OFF (FG_OFF  + BS*NA)       // 11424000

typedef unsigned long long u64;

// ---- scratch (zero at module load; self-resetting across graph replays) ----
__device__ int          g_cnt [BS*NA];     // claims per anchor      (kC resets)
__device__ int          g_maxj[BS*NA];     // max(NMAX-j) of claims  (kC resets)
__device__ int          g_tgt [BS*NA];
__device__ int          g_lab [BS*NA];     // label or -1
__device__ float        g_alpos[BS*NA];
__device__ unsigned int g_posal[BS*NMAX];  // zeroed by kAB each run
__device__ unsigned int g_posov[BS*NMAX];  // zeroed by kAB each run

// IoU given precomputed center distance d (matches reference formulas)
__device__ __forceinline__ float circle_iou_d(float d, float r1, float r2)
{
    float a1 = PIF*r1*r1, a2 = PIF*r2*r2;
    float d2 = d*d;
    float cos1 = fminf(fmaxf((d2 + r1*r1 - r2*r2) / (2.f*d*r1 + EPSF), -1.f), 1.f);
    float cos2 = fminf(fmaxf((d2 + r2*r2 - r1*r1) / (2.f*d*r2 + EPSF), -1.f), 1.f);
    float tri  = fmaxf((r1+r2-d)*(d+r1-r2)*(d-r1+r2)*(d+r1+r2), 0.f);
    float lens = r1*r1*acosf(cos1) + r2*r2*acosf(cos2) - 0.5f*sqrtf(tri);
    float rmin = fminf(r1, r2);
    float inter = (d >= r1 + r2) ? 0.f
                : ((d <= fabsf(r1 - r2)) ? PIF*rmin*rmin : lens);
    return inter / (a1 + a2 - inter + EPSF);
}

__device__ __forceinline__ float circle_iou_f(float gx, float gy, float gr,
                                              float px, float py, float pr)
{
    float ddx = gx - px, ddy = gy - py;
    float d  = sqrtf(ddx*ddx + ddy*ddy + EPSF);
    return circle_iou_d(d, gr, pr);
}

__device__ __forceinline__ void decode_anchor(int a, float& ax, float& ay)
{
    if (a < 6400)      { int y = a / 80, x = a - y*80;             ax = (x+0.5f)*8.f;  ay = (y+0.5f)*8.f;  }
    else if (a < 8000) { int r = a-6400; int y = r/40, x = r-y*40; ax = (x+0.5f)*16.f; ay = (y+0.5f)*16.f; }
    else               { int r = a-8000; int y = r/20, x = r-y*20; ax = (x+0.5f)*32.f; ay = (y+0.5f)*32.f; }
}

// ============================================================
// kAB: one BLOCK (4 warps / 128 threads) per (b,j) GT row.
// PURE compute now (no fill): two-pass candidate processing with
// batched prefetch (MLP ~24), per-lane sorted top-6 u64 keys,
// per-warp REDUX pop-merge -> block merge -> claim scatter.
// ============================================================
#define ROW_WARPS   4
#define ROW_THREADS (ROW_WARPS*32)
#define NITER       6                          // ceil(649/128)=6 worst case

__global__ void __launch_bounds__(ROW_THREADS)
kAB(const float* __restrict__ ps, const float* __restrict__ pc,
    const int* __restrict__ gl, const float* __restrict__ gb,
    const float* __restrict__ mg)
{
    const int row = blockIdx.x;                  // b*NMAX + j
    const int t = threadIdx.x;
    if (t == 0) { g_posal[row] = 0u; g_posov[row] = 0u; }

    if (!(mg[row] > 0.f)) return;                // invalid row: nothing to do
    const int lane = t & 31;
    const int wid  = t >> 5;
    const int b = row / NMAX;
    const int j = row - b*NMAX;

    const float gx = gb[row*3+0], gy = gb[row*3+1], gr = gb[row*3+2];
    int lab = gl[row]; lab = max(0, min(NC-1, lab));
    const int pcBase = b*NA;

    // per-scale candidate boxes
    int x0v[3], y0v[3], cwv[3], ccv[3];
    const float ssv[3] = {8.f, 16.f, 32.f};
    const int   nnv[3] = {80, 40, 20};
    int total = 0;
    #pragma unroll
    for (int s = 0; s < 3; s++) {
        int xl = max(0, (int)floorf((gx - gr)/ssv[s] - 0.5f));
        int xh = min(nnv[s]-1, (int)ceilf ((gx + gr)/ssv[s] - 0.5f));
        int yl = max(0, (int)floorf((gy - gr)/ssv[s] - 0.5f));
        int yh = min(nnv[s]-1, (int)ceilf ((gy + gr)/ssv[s] - 0.5f));
        x0v[s] = xl; y0v[s] = yl;
        cwv[s] = max(0, xh - xl + 1);
        int chh = max(0, yh - yl + 1);
        ccv[s] = total;
        total += cwv[s]*chh;
    }

    // ---- pass 1: decode + batched prefetch (all loads in flight) ----
    int   aA [NITER]; bool okA[NITER];
    float pxA[NITER], pyA[NITER], prA[NITER], scA[NITER];
    #pragma unroll
    for (int it = 0; it < NITER; it++) {
        int i = t + it*ROW_THREADS;
        bool valid = (i < total);
        int iS = valid ? i : 0;

        int sc3 = (iS >= ccv[2]) ? 2 : ((iS >= ccv[1]) ? 1 : 0);
        int r  = iS - ((sc3==2) ? ccv[2] : ((sc3==1) ? ccv[1] : 0));
        int cw = (sc3==2) ? cwv[2] : ((sc3==1) ? cwv[1] : cwv[0]);
        float sf = (sc3==2) ? 32.f : ((sc3==1) ? 16.f : 8.f);
        int nnc  = (sc3==2) ? 20 : ((sc3==1) ? 40 : 80);
        int bbs  = (sc3==2) ? 8000 : ((sc3==1) ? 6400 : 0);
        int xl   = (sc3==2) ? x0v[2] : ((sc3==1) ? x0v[1] : x0v[0]);
        int yl   = (sc3==2) ? y0v[2] : ((sc3==1) ? y0v[1] : y0v[0]);

        // exact div-free decode: yy = r / cw  (r<=649, cw<=21)
        int yy = (int)(((float)r + 0.5f) / (float)cw);
        int xx = r - yy*cw;
        int gxi = xl + xx, gyi = yl + yy;
        float ax = (gxi + 0.5f) * sf;
        float ay = (gyi + 0.5f) * sf;
        int a = bbs + gyi*nnc + gxi;

        float dx = gx - ax, dy = gy - ay;
        bool ok = valid && (sqrtf(dx*dx + dy*dy) <= gr);
        aA[it] = a; okA[it] = ok;

        int aS = ok ? a : 0;
        int pa3 = (pcBase + aS)*3;
        pxA[it] = __ldg(pc + pa3 + 0);
        pyA[it] = __ldg(pc + pa3 + 1);
        prA[it] = __ldg(pc + pa3 + 2);
        scA[it] = __ldg(ps + (pcBase + aS)*NC + lab);
    }

    // per-lane sorted top-6 of 64-bit keys (desc). key=0 = empty.
    u64 s0=0,s1=0,s2=0,s3=0,s4=0,s5=0;

    // ---- pass 2: pure compute ----
    #pragma unroll
    for (int it = 0; it < NITER; it++) {
        if (!okA[it]) continue;
        float ddx = gx - pxA[it], ddy = gy - pyA[it];
        float d = sqrtf(ddx*ddx + ddy*ddy + EPSF);
        float pr = prA[it];
        if (d >= gr + pr) continue;              // overlap gate (rare pass)

        float iou = circle_iou_d(d, gr, pr);
        float o2 = iou*iou;
        float v = scA[it] * (o2*o2*o2);
        if (v <= 0.f) continue;

        u64 k = ((u64)__float_as_uint(v) << 32)
              | (unsigned int)(~(unsigned int)aA[it]);
        if (k > s5) {
            s5 = k; u64 tt;
            if (s5 > s4) { tt=s4; s4=s5; s5=tt; }
            if (s4 > s3) { tt=s3; s3=s4; s4=tt; }
            if (s3 > s2) { tt=s2; s2=s3; s3=tt; }
            if (s2 > s1) { tt=s1; s1=s2; s2=tt; }
            if (s1 > s0) { tt=s0; s0=s1; s1=tt; }
        }
    }

    // ---- per-warp pop-merge: 13 rounds, warp max of per-lane head s0 ----
    __shared__ u64 sm_keys[ROW_WARPS*TOPK];
    u64 wkey = 0;
    for (int r = 0; r < TOPK; r++) {
        unsigned hi  = (unsigned)(s0 >> 32);
        unsigned mhi = __reduce_max_sync(0xffffffffu, hi);
        unsigned lo  = (hi == mhi) ? (unsigned)(s0 & 0xffffffffu) : 0u;
        unsigned mlo = __reduce_max_sync(0xffffffffu, lo);
        u64 m = ((u64)mhi << 32) | mlo;
        if (m == 0ull) break;                    // warp-uniform
        if (lane == r) wkey = m;
        if (s0 == m) { s0=s1; s1=s2; s2=s3; s3=s4; s4=s5; s5=0; }
    }
    if (lane < TOPK) sm_keys[wid*TOPK + lane] = wkey;
    __syncthreads();

    // ---- block merge + fill-slots + scatter: warp 0 only ----
    if (wid != 0) return;

    u64 ka = sm_keys[lane];                       // lane < 32 <= 52
    u64 kb = (lane + 32 < ROW_WARPS*TOPK) ? sm_keys[lane + 32] : 0ull;
    if (kb > ka) { u64 tt = ka; ka = kb; kb = tt; }

    int seli = 0x7fffffff;
    int npos = TOPK;
    for (int r = 0; r < TOPK; r++) {
        unsigned hi  = (unsigned)(ka >> 32);
        unsigned mhi = __reduce_max_sync(0xffffffffu, hi);
        unsigned lo  = (hi == mhi) ? (unsigned)(ka & 0xffffffffu) : 0u;
        unsigned mlo = __reduce_max_sync(0xffffffffu, lo);
        u64 m = ((u64)mhi << 32) | mlo;
        if (m == 0ull) { npos = r; break; }
        if (lane == r) seli = (int)(~mlo);
        if (ka == m) { ka = kb; kb = 0ull; }
    }

    // gather positive indices to every lane
    int pidx[TOPK];
    #pragma unroll
    for (int k = 0; k < TOPK; k++)
        pidx[k] = __shfl_sync(0xffffffffu, seli, k);

    // fill remaining slots: smallest global indices not among positives
    if (lane >= npos && lane < TOPK) {
        int need = lane - npos;
        int m = 0;
        while (true) {
            bool inP = false;
            #pragma unroll
            for (int k = 0; k < TOPK; k++)
                if (k < npos && pidx[k] == m) inP = true;
            if (!inP) { if (need == 0) break; need--; }
            m++;
        }
        seli = m;
    }

    // claim scatter for selected anchors passing the inside-GT test
    if (lane < TOPK) {
        int a = seli;
        float ax, ay;
        decode_anchor(a, ax, ay);
        float dx = gx - ax, dy = gy - ay;
        if (sqrtf(dx*dx + dy*dy) <= gr) {
            int pa = b*NA + a;
            atomicAdd(&g_cnt[pa], 1);
            atomicMax(&g_maxj[pa], NMAX - j);    // encodes min j; 0 = none
        }
    }
}

// ============================================================
// kC: per (b,a) — conflict resolution, gathers, row maxima,
//     scratch self-reset for next graph replay
// ============================================================
__global__ void kC(const float* __restrict__ ps, const float* __restrict__ pc,
                   const float* __restrict__ anc, const int* __restrict__ gl,
                   const float* __restrict__ gb, const float* __restrict__ mg,
                   float* __restrict__ out)
{
    int a = blockIdx.x * blockDim.x + threadIdx.x;
    int b = blockIdx.y;
    if (a >= NA) return;
    int pa = b * NA + a;

    float ax = anc[a*2+0], ay = anc[a*2+1];
    float px = pc[pa*3+0], py = pc[pa*3+1], pr = pc[pa*3+2];

    int cnt  = g_cnt[pa];
    int maxv = g_maxj[pa];
    if (cnt) { g_cnt[pa] = 0; g_maxj[pa] = 0; }   // reset for next replay

    int tgt, fg;
    if (cnt > 1) {
        float bov = -1.f; int jm = 0;
        for (int jj = 0; jj < NMAX; jj++) {
            int row = b * NMAX + jj;
            float ov = 0.f;
            if (mg[row] > 0.f) {
                float gx = gb[row*3+0], gy = gb[row*3+1], gr = gb[row*3+2];
                float dx = gx - ax, dy = gy - ay;
                if (sqrtf(dx*dx + dy*dy) <= gr)
                    ov = circle_iou_f(gx, gy, gr, px, py, pr);
            }
            if (ov > bov) { bov = ov; jm = jj; }
        }
        tgt = jm; fg = 1;
    } else if (cnt == 1) {
        tgt = NMAX - maxv; fg = 1;
    } else {
        tgt = 0; fg = 0;
    }

    int row = b * NMAX + tgt;
    int labRaw = gl[row];
    int labOut = max(labRaw, 0);

    out[LAB_OFF + pa] = (float)labOut;
    out[CIR_OFF + pa*3 + 0] = gb[row*3+0];
    out[CIR_OFF + pa*3 + 1] = gb[row*3+1];
    out[CIR_OFF + pa*3 + 2] = gb[row*3+2];
    out[FG_OFF  + pa] = (float)fg;
    out[TGT_OFF + pa] = (float)tgt;

    g_tgt[pa] = tgt;
    float alv = 0.f;
    int labSc = -1;
    if (fg) {
        float gx = gb[row*3+0], gy = gb[row*3+1], gr = gb[row*3+2];
        float dx = gx - ax, dy = gy - ay;
        float ov = 0.f;
        if (mg[row] > 0.f && sqrtf(dx*dx + dy*dy) <= gr)
            ov = circle_iou_f(gx, gy, gr, px, py, pr);
        int lc = max(0, min(NC-1, labRaw));
        float sc = ps[pa*NC + lc];
        float o2 = ov*ov;
        alv = sc * (o2*o2*o2);
        labSc = labOut;
        if (alv > 0.f) atomicMax(&g_posal[row], __float_as_uint(alv));
        if (ov  > 0.f) atomicMax(&g_posov[row], __float_as_uint(ov));
    }
    g_alpos[pa] = alv;
    g_lab[pa]   = labSc;
}

// ============================================================
// kS: score-region writer. Each block owns 256 contiguous anchors:
// coalesced zero-fill of its 20480-float segment, sync, then the
// sparse per-anchor norm store. 525 blocks cover BS*NA exactly.
// ============================================================
#define KS_TPB    256
#define KS_SEGF4  (KS_TPB*NC/4)                  // 5120 float4 per block

__global__ void __launch_bounds__(KS_TPB)
kS(float* __restrict__ out)
{
    const int blk = blockIdx.x;
    const int tid = threadIdx.x;

    // coalesced zero-fill of this block's segment
    float4 z = make_float4(0.f, 0.f, 0.f, 0.f);
    float4* dst = (float4*)(out + SC_OFF) + (size_t)blk * KS_SEGF4;
    #pragma unroll
    for (int i = 0; i < KS_SEGF4/KS_TPB; i++)
        dst[i*KS_TPB + tid] = z;
    __syncthreads();

    // sparse scatter
    int pa = blk * KS_TPB + tid;
    int lab = g_lab[pa];
    if (lab < 0) return;
    int b = pa / NA;
    int row = b * NMAX + g_tgt[pa];
    float posal = __uint_as_float(g_posal[row]);
    float posov = __uint_as_float(g_posov[row]);
    float nrm = g_alpos[pa] * posov / (posal + EPSF);
    out[SC_OFF + pa*NC + lab] = nrm;
}

// ============================================================
extern "C" void kernel_launch(void* const* d_in, const int* in_sizes, int n_in,
                              void* d_out, int out_size)
{
    const float* pd_scores  = (const float*)d_in[0];
    const float* pd_circles = (const float*)d_in[1];
    const float* anc_points = (const float*)d_in[2];
    const int*   gt_labels  = (const int*)  d_in[3];
    const float* gt_bboxes  = (const float*)d_in[4];
    const float* mask_gt    = (const float*)d_in[5];
    float* out = (float*)d_out;

    kAB<<<BS*NMAX, ROW_THREADS>>>(pd_scores, pd_circles,
                                  gt_labels, gt_bboxes, mask_gt);

    dim3 gC((NA + 255)/256, BS);
    kC<<<gC, 256>>>(pd_scores, pd_circles, anc_points,
                    gt_labels, gt_bboxes, mask_gt, out);

    kS<<<(BS*NA)/KS_TPB, KS_TPB>>>(out);
}

// round 14
// speedup vs baseline: 1.7333x; 1.7333x over previous
#include <cuda_runtime.h>
#include <cuda_bf16.h>
#include <math.h>

#define BS   16
#define NA   8400
#define NMAX 64
#define NC   80
#define TOPK 13
#define EPSF 1e-9f
#define PIF  3.14159265358979323846f

// Output layout (flattened, reference return order, all f32)
#define LAB_OFF 0
#define CIR_OFF (BS*NA)                 // 134400
#define SC_OFF  (CIR_OFF + BS*NA*3)     // 537600
#define FG_OFF  (SC_OFF  + BS*NA*NC)    // 11289600
#define TGT_OFF (FG_OFF  + BS*NA)       // 11424000

typedef unsigned long long u64;

// ---- scratch (zero at module load; self-resetting across graph replays) ----
__device__ int          g_cnt [BS*NA];     // claims per anchor      (kC resets)
__device__ int          g_maxj[BS*NA];     // max(NMAX-j) of claims  (kC resets)
__device__ u64          g_best[BS*NA];     // (iou_bits<<32)|(63-j)  (kS resets)
__device__ int          g_tgt [BS*NA];
__device__ int          g_lab [BS*NA];     // label or -1
__device__ float        g_alpos[BS*NA];
__device__ unsigned int g_posal[BS*NMAX];  // zeroed by kAB each run
__device__ unsigned int g_posov[BS*NMAX];  // zeroed by kAB each run

// IoU given precomputed center distance d (matches reference formulas)
__device__ __forceinline__ float circle_iou_d(float d, float r1, float r2)
{
    float a1 = PIF*r1*r1, a2 = PIF*r2*r2;
    float d2 = d*d;
    float cos1 = fminf(fmaxf((d2 + r1*r1 - r2*r2) / (2.f*d*r1 + EPSF), -1.f), 1.f);
    float cos2 = fminf(fmaxf((d2 + r2*r2 - r1*r1) / (2.f*d*r2 + EPSF), -1.f), 1.f);
    float tri  = fmaxf((r1+r2-d)*(d+r1-r2)*(d-r1+r2)*(d+r1+r2), 0.f);
    float lens = r1*r1*acosf(cos1) + r2*r2*acosf(cos2) - 0.5f*sqrtf(tri);
    float rmin = fminf(r1, r2);
    float inter = (d >= r1 + r2) ? 0.f
                : ((d <= fabsf(r1 - r2)) ? PIF*rmin*rmin : lens);
    return inter / (a1 + a2 - inter + EPSF);
}

__device__ __forceinline__ float circle_iou_f(float gx, float gy, float gr,
                                              float px, float py, float pr)
{
    float ddx = gx - px, ddy = gy - py;
    float d  = sqrtf(ddx*ddx + ddy*ddy + EPSF);
    return circle_iou_d(d, gr, pr);
}

__device__ __forceinline__ void decode_anchor(int a, float& ax, float& ay)
{
    if (a < 6400)      { int y = a / 80, x = a - y*80;             ax = (x+0.5f)*8.f;  ay = (y+0.5f)*8.f;  }
    else if (a < 8000) { int r = a-6400; int y = r/40, x = r-y*40; ax = (x+0.5f)*16.f; ay = (y+0.5f)*16.f; }
    else               { int r = a-8000; int y = r/20, x = r-y*20; ax = (x+0.5f)*32.f; ay = (y+0.5f)*32.f; }
}

// ============================================================
// kAB: one BLOCK (4 warps / 128 threads) per (b,j) GT row.
// Two-pass candidate processing with batched prefetch; per-lane sorted
// top-6 u64 keys; per-warp REDUX pop-merge -> block merge -> claim
// scatter. Records per-anchor argmax-overlap key (g_best) for kC's
// contested path. Segment zero-fill at block tail (R12 placement:
// invalid-row blocks fill early, overlapping valid blocks' compute).
// ============================================================
#define ROW_WARPS   4
#define ROW_THREADS (ROW_WARPS*32)
#define NITER       6                          // ceil(649/128)=6 worst case
#define SC_F4       (BS*NA*NC/4)               // 2,688,000 float4s
#define SEG_F4      (SC_F4/1024)               // 2625 per block

__device__ __forceinline__ void fill_seg(float* __restrict__ out, int row, int t)
{
    float4 z = make_float4(0.f, 0.f, 0.f, 0.f);
    float4* dst = (float4*)(out + SC_OFF) + row*SEG_F4;
    for (int i = t; i < SEG_F4; i += ROW_THREADS)
        dst[i] = z;
}

__global__ void __launch_bounds__(ROW_THREADS)
kAB(const float* __restrict__ ps, const float* __restrict__ pc,
    const int* __restrict__ gl, const float* __restrict__ gb,
    const float* __restrict__ mg, float* __restrict__ out)
{
    const int row = blockIdx.x;                  // b*NMAX + j
    const int t = threadIdx.x;
    if (t == 0) { g_posal[row] = 0u; g_posov[row] = 0u; }

    if (!(mg[row] > 0.f)) {                      // invalid row: fill + exit
        fill_seg(out, row, t);
        return;
    }
    const int lane = t & 31;
    const int wid  = t >> 5;
    const int b = row / NMAX;
    const int j = row - b*NMAX;

    const float gx = gb[row*3+0], gy = gb[row*3+1], gr = gb[row*3+2];
    int lab = gl[row]; lab = max(0, min(NC-1, lab));
    const int pcBase = b*NA;

    // per-scale candidate boxes
    int x0v[3], y0v[3], cwv[3], ccv[3];
    const float ssv[3] = {8.f, 16.f, 32.f};
    const int   nnv[3] = {80, 40, 20};
    int total = 0;
    #pragma unroll
    for (int s = 0; s < 3; s++) {
        int xl = max(0, (int)floorf((gx - gr)/ssv[s] - 0.5f));
        int xh = min(nnv[s]-1, (int)ceilf ((gx + gr)/ssv[s] - 0.5f));
        int yl = max(0, (int)floorf((gy - gr)/ssv[s] - 0.5f));
        int yh = min(nnv[s]-1, (int)ceilf ((gy + gr)/ssv[s] - 0.5f));
        x0v[s] = xl; y0v[s] = yl;
        cwv[s] = max(0, xh - xl + 1);
        int chh = max(0, yh - yl + 1);
        ccv[s] = total;
        total += cwv[s]*chh;
    }

    // ---- pass 1: decode + batched prefetch (all loads in flight) ----
    int   aA [NITER]; bool okA[NITER];
    float pxA[NITER], pyA[NITER], prA[NITER], scA[NITER];
    #pragma unroll
    for (int it = 0; it < NITER; it++) {
        int i = t + it*ROW_THREADS;
        bool valid = (i < total);
        int iS = valid ? i : 0;

        int sc3 = (iS >= ccv[2]) ? 2 : ((iS >= ccv[1]) ? 1 : 0);
        int r  = iS - ((sc3==2) ? ccv[2] : ((sc3==1) ? ccv[1] : 0));
        int cw = (sc3==2) ? cwv[2] : ((sc3==1) ? cwv[1] : cwv[0]);
        float sf = (sc3==2) ? 32.f : ((sc3==1) ? 16.f : 8.f);
        int nnc  = (sc3==2) ? 20 : ((sc3==1) ? 40 : 80);
        int bbs  = (sc3==2) ? 8000 : ((sc3==1) ? 6400 : 0);
        int xl   = (sc3==2) ? x0v[2] : ((sc3==1) ? x0v[1] : x0v[0]);
        int yl   = (sc3==2) ? y0v[2] : ((sc3==1) ? y0v[1] : y0v[0]);

        // exact div-free decode: yy = r / cw  (r<=649, cw<=21)
        int yy = (int)(((float)r + 0.5f) / (float)cw);
        int xx = r - yy*cw;
        int gxi = xl + xx, gyi = yl + yy;
        float ax = (gxi + 0.5f) * sf;
        float ay = (gyi + 0.5f) * sf;
        int a = bbs + gyi*nnc + gxi;

        float dx = gx - ax, dy = gy - ay;
        bool ok = valid && (sqrtf(dx*dx + dy*dy) <= gr);
        aA[it] = a; okA[it] = ok;

        int aS = ok ? a : 0;
        int pa3 = (pcBase + aS)*3;
        pxA[it] = __ldg(pc + pa3 + 0);
        pyA[it] = __ldg(pc + pa3 + 1);
        prA[it] = __ldg(pc + pa3 + 2);
        scA[it] = __ldg(ps + (pcBase + aS)*NC + lab);
    }

    // per-lane sorted top-6 of 64-bit keys (desc). key=0 = empty.
    u64 s0=0,s1=0,s2=0,s3=0,s4=0,s5=0;

    // ---- pass 2: pure compute + argmax-overlap recording ----
    #pragma unroll
    for (int it = 0; it < NITER; it++) {
        if (!okA[it]) continue;
        float ddx = gx - pxA[it], ddy = gy - pyA[it];
        float d = sqrtf(ddx*ddx + ddy*ddy + EPSF);
        float pr = prA[it];
        if (d >= gr + pr) continue;              // overlap gate (rare pass)

        float iou = circle_iou_d(d, gr, pr);
        if (iou > 0.f) {
            // record (iou desc, j asc) argmax key for this anchor
            u64 bk = ((u64)__float_as_uint(iou) << 32) | (u64)(NMAX-1 - j);
            atomicMax(&g_best[pcBase + aA[it]], bk);
        }
        float o2 = iou*iou;
        float v = scA[it] * (o2*o2*o2);
        if (v <= 0.f) continue;

        u64 k = ((u64)__float_as_uint(v) << 32)
              | (unsigned int)(~(unsigned int)aA[it]);
        if (k > s5) {
            s5 = k; u64 tt;
            if (s5 > s4) { tt=s4; s4=s5; s5=tt; }
            if (s4 > s3) { tt=s3; s3=s4; s4=tt; }
            if (s3 > s2) { tt=s2; s2=s3; s3=tt; }
            if (s2 > s1) { tt=s1; s1=s2; s2=tt; }
            if (s1 > s0) { tt=s0; s0=s1; s1=tt; }
        }
    }

    // ---- per-warp pop-merge: 13 rounds, warp max of per-lane head s0 ----
    __shared__ u64 sm_keys[ROW_WARPS*TOPK];
    u64 wkey = 0;
    for (int r = 0; r < TOPK; r++) {
        unsigned hi  = (unsigned)(s0 >> 32);
        unsigned mhi = __reduce_max_sync(0xffffffffu, hi);
        unsigned lo  = (hi == mhi) ? (unsigned)(s0 & 0xffffffffu) : 0u;
        unsigned mlo = __reduce_max_sync(0xffffffffu, lo);
        u64 m = ((u64)mhi << 32) | mlo;
        if (m == 0ull) break;                    // warp-uniform
        if (lane == r) wkey = m;
        if (s0 == m) { s0=s1; s1=s2; s2=s3; s3=s4; s4=s5; s5=0; }
    }
    if (lane < TOPK) sm_keys[wid*TOPK + lane] = wkey;
    __syncthreads();

    // ---- block merge + fill-slots + scatter: warp 0 only ----
    if (wid == 0) {
        u64 ka = sm_keys[lane];                   // lane < 32 <= 52
        u64 kb = (lane + 32 < ROW_WARPS*TOPK) ? sm_keys[lane + 32] : 0ull;
        if (kb > ka) { u64 tt = ka; ka = kb; kb = tt; }

        int seli = 0x7fffffff;
        int npos = TOPK;
        for (int r = 0; r < TOPK; r++) {
            unsigned hi  = (unsigned)(ka >> 32);
            unsigned mhi = __reduce_max_sync(0xffffffffu, hi);
            unsigned lo  = (hi == mhi) ? (unsigned)(ka & 0xffffffffu) : 0u;
            unsigned mlo = __reduce_max_sync(0xffffffffu, lo);
            u64 m = ((u64)mhi << 32) | mlo;
            if (m == 0ull) { npos = r; break; }
            if (lane == r) seli = (int)(~mlo);
            if (ka == m) { ka = kb; kb = 0ull; }
        }

        // gather positive indices to every lane
        int pidx[TOPK];
        #pragma unroll
        for (int k = 0; k < TOPK; k++)
            pidx[k] = __shfl_sync(0xffffffffu, seli, k);

        // fill remaining slots: smallest global indices not among positives
        if (lane >= npos && lane < TOPK) {
            int need = lane - npos;
            int m = 0;
            while (true) {
                bool inP = false;
                #pragma unroll
                for (int k = 0; k < TOPK; k++)
                    if (k < npos && pidx[k] == m) inP = true;
                if (!inP) { if (need == 0) break; need--; }
                m++;
            }
            seli = m;
        }

        // claim scatter for selected anchors passing the inside-GT test
        if (lane < TOPK) {
            int a = seli;
            float ax, ay;
            decode_anchor(a, ax, ay);
            float dx = gx - ax, dy = gy - ay;
            if (sqrtf(dx*dx + dy*dy) <= gr) {
                int pa = b*NA + a;
                atomicAdd(&g_cnt[pa], 1);
                atomicMax(&g_maxj[pa], NMAX - j); // encodes min j; 0 = none
            }
        }
    }

    // valid-row blocks fill their segment last
    fill_seg(out, row, t);
}

// ============================================================
// kC: per (b,a) — conflict resolution (g_best lookup, no loop),
// gathers, row maxima, scratch self-reset for next graph replay
// ============================================================
__global__ void kC(const float* __restrict__ ps, const float* __restrict__ pc,
                   const float* __restrict__ anc, const int* __restrict__ gl,
                   const float* __restrict__ gb, const float* __restrict__ mg,
                   float* __restrict__ out)
{
    int a = blockIdx.x * blockDim.x + threadIdx.x;
    int b = blockIdx.y;
    if (a >= NA) return;
    int pa = b * NA + a;

    int cnt  = g_cnt[pa];
    int maxv = g_maxj[pa];
    if (cnt) { g_cnt[pa] = 0; g_maxj[pa] = 0; }   // reset for next replay

    int tgt, fg;
    if (cnt > 1) {
        // argmax_j overlaps — precomputed by kAB (first-max semantics)
        u64 bk = g_best[pa];
        tgt = bk ? (NMAX-1 - (int)(bk & 63u)) : 0;
        fg = 1;
    } else if (cnt == 1) {
        tgt = NMAX - maxv; fg = 1;
    } else {
        tgt = 0; fg = 0;
    }

    int row = b * NMAX + tgt;
    int labRaw = gl[row];
    int labOut = max(labRaw, 0);

    out[LAB_OFF + pa] = (float)labOut;
    out[CIR_OFF + pa*3 + 0] = gb[row*3+0];
    out[CIR_OFF + pa*3 + 1] = gb[row*3+1];
    out[CIR_OFF + pa*3 + 2] = gb[row*3+2];
    out[FG_OFF  + pa] = (float)fg;
    out[TGT_OFF + pa] = (float)tgt;

    g_tgt[pa] = tgt;
    float alv = 0.f;
    int labSc = -1;
    if (fg) {
        float ax = anc[a*2+0], ay = anc[a*2+1];
        float px = pc[pa*3+0], py = pc[pa*3+1], pr = pc[pa*3+2];
        float gx = gb[row*3+0], gy = gb[row*3+1], gr = gb[row*3+2];
        float dx = gx - ax, dy = gy - ay;
        float ov = 0.f;
        if (mg[row] > 0.f && sqrtf(dx*dx + dy*dy) <= gr)
            ov = circle_iou_f(gx, gy, gr, px, py, pr);
        int lc = max(0, min(NC-1, labRaw));
        float sc = ps[pa*NC + lc];
        float o2 = ov*ov;
        alv = sc * (o2*o2*o2);
        labSc = labOut;
        if (alv > 0.f) atomicMax(&g_posal[row], __float_as_uint(alv));
        if (ov  > 0.f) atomicMax(&g_posov[row], __float_as_uint(ov));
    }
    g_alpos[pa] = alv;
    g_lab[pa]   = labSc;
}

// ============================================================
// kS: sparse score scatter (zeros laid down by kAB) + g_best reset.
// ============================================================
__global__ void kS(float* __restrict__ out)
{
    int pa = blockIdx.x * blockDim.x + threadIdx.x;
    if (pa >= BS*NA) return;
    if (g_best[pa]) g_best[pa] = 0ull;            // reset for next replay
    int lab = g_lab[pa];
    if (lab < 0) return;
    int b = pa / NA;
    int row = b * NMAX + g_tgt[pa];
    float posal = __uint_as_float(g_posal[row]);
    float posov = __uint_as_float(g_posov[row]);
    float nrm = g_alpos[pa] * posov / (posal + EPSF);
    out[SC_OFF + pa*NC + lab] = nrm;
}

// ============================================================
extern "C" void kernel_launch(void* const* d_in, const int* in_sizes, int n_in,
                              void* d_out, int out_size)
{
    const float* pd_scores  = (const float*)d_in[0];
    const float* pd_circles = (const float*)d_in[1];
    const float* anc_points = (const float*)d_in[2];
    const int*   gt_labels  = (const int*)  d_in[3];
    const float* gt_bboxes  = (const float*)d_in[4];
    const float* mask_gt    = (const float*)d_in[5];
    float* out = (float*)d_out;

    kAB<<<BS*NMAX, ROW_THREADS>>>(pd_scores, pd_circles,
                                  gt_labels, gt_bboxes, mask_gt, out);

    dim3 gC((NA + 255)/256, BS);
    kC<<<gC, 256>>>(pd_scores, pd_circles, anc_points,
                    gt_labels, gt_bboxes, mask_gt, out);

    kS<<<(BS*NA + 255)/256, 256>>>(out);
}